// round 5
// baseline (speedup 1.0000x reference)
#include <cuda_runtime.h>
#include <cstdint>

// Problem constants (fixed by the reference)
#define B_    2
#define T_    512
#define D_    768
#define E_    256
#define P_    65536
#define H1_   768
#define H2_   384
#define NL_   5
#define ROWS_ (B_*E_)          // 512 fused (b,e) rows

// ---------------- scratch (static device globals; no allocation) ------------
__device__ float g_pooled[ROWS_*D_];       // mean-pooled spans        [512,768]
__device__ float g_eph[NL_*H1_];           // emb @ Wh1[768:]          [5,768]
__device__ float g_ept[NL_*H1_];           // emb @ Wt1[768:]          [5,768]
__device__ float g_h1h[ROWS_*H1_];         // head layer-1 out         [512,768]
__device__ float g_h1t[ROWS_*H1_];         // tail layer-1 out         [512,768]
__device__ float g_head[ROWS_*H2_];        // head_all                 [512,384]
__device__ float g_tail[ROWS_*H2_];        // tail_all                 [512,384]
__device__ float g_u[ROWS_*2*H2_];         // head @ W_bil : [row][o*384+j]
__device__ float g_V[B_*2*E_*E_];          // dense biaffine table [b][o][hh][tt]
__device__ float g_lh[ROWS_*2];            // head @ W_lin[:384]
__device__ float g_lt[ROWS_*2];            // tail @ W_lin[384:]

// ---------------- tf32 helpers ----------------------------------------------
__device__ __forceinline__ uint32_t f2tf32(float x) {
    uint32_t r;
    asm("cvt.rna.tf32.f32 %0, %1;" : "=r"(r) : "f"(x));
    return r;
}
__device__ __forceinline__ void mma_tf32(float c[4],
                                         const uint32_t a[4],
                                         const uint32_t b[2]) {
    asm volatile(
        "mma.sync.aligned.m16n8k8.row.col.f32.tf32.tf32.f32 "
        "{%0,%1,%2,%3}, {%4,%5,%6,%7}, {%8,%9}, {%0,%1,%2,%3};"
        : "+f"(c[0]), "+f"(c[1]), "+f"(c[2]), "+f"(c[3])
        : "r"(a[0]), "r"(a[1]), "r"(a[2]), "r"(a[3]), "r"(b[0]), "r"(b[1]));
}

// ---------------- 1) span mean-pooling --------------------------------------
__global__ void pool_kernel(const float* __restrict__ hs,
                            const int* __restrict__ st,
                            const int* __restrict__ en) {
    int be = blockIdx.x;             // 0..511
    int b  = be >> 8;
    int s  = st[be];
    int len = en[be] - s;
    int cl  = len < 1 ? 1 : len;
    float inv = 1.0f / (float)cl;
    const float* base = hs + ((size_t)(b*T_ + s))*D_;
    for (int d = threadIdx.x; d < D_; d += blockDim.x) {
        float acc = 0.f;
        for (int t = 0; t < len; t++) acc += base[(size_t)t*D_ + d];
        g_pooled[(size_t)be*D_ + d] = acc * inv;
    }
}

// ---------------- 2) per-label projection through W1[768:] for BOTH nets ----
__global__ void labelproj2_kernel(const float* __restrict__ emb,
                                  const float* __restrict__ Wh1,
                                  const float* __restrict__ Wt1) {
    int gid = blockIdx.x*blockDim.x + threadIdx.x;  // 2*5*768 = 7680
    if (gid >= 2*NL_*H1_) return;
    int half = gid / (NL_*H1_);
    int r    = gid - half*(NL_*H1_);
    int l = r / H1_, n = r - l*H1_;
    const float* W1 = half ? Wt1 : Wh1;
    const float* wp = W1 + (size_t)D_*H1_ + n;      // rows 768..1535, col n
    const float* ep = emb + (size_t)l*D_;
    float acc = 0.f;
    #pragma unroll 4
    for (int k = 0; k < D_; k++) acc += ep[k] * wp[(size_t)k*H1_];
    if (half) g_ept[r] = acc; else g_eph[r] = acc;
}

// ---------------- 3xTF32 tensor-core GEMM core ------------------------------
// C = act(A[M,K] @ B[K,N] + bias (+ lbias[label[row]]))
// Block tile 64x64, k-tile 16, 256 threads (8 warps: 2 m-warps x 4 n-warps),
// warp tile 32x16 (2 m-frags x 2 n-frags of m16n8k8).
// Each input split x = hi + lo in tf32 during smem staging; accumulate
// hi*hi + hi*lo + lo*hi in fp32 -> ~fp32 accuracy on the tensor pipe.
// B addressing:
//   bnt==0 : B[k][n] at W + (n/segw)*segstride + k*ldb + (n%segw)
//   bnt==1 : B[n][k] at W + n*ldb + k          (NT form)
// M%64==0, N%64==0, segw%64==0, K%16==0 required.
__device__ __forceinline__ void gemm3tf32_core(
    const float* __restrict__ A, int lda,
    const float* __restrict__ W, int ldb, int segw, int segstride, int bnt,
    const float* __restrict__ bias,
    const int* __restrict__ labels, const float* __restrict__ lb,
    float* __restrict__ C, int ldc, int N, int K, int relu)
{
    __shared__ uint32_t AsH[2][64][20];
    __shared__ uint32_t AsL[2][64][20];
    __shared__ uint32_t BsH[2][64][20];
    __shared__ uint32_t BsL[2][64][20];

    const int tid = threadIdx.x;
    const int bm = blockIdx.y * 64, bn = blockIdx.x * 64;
    const int lane = tid & 31;
    const int wid  = tid >> 5;
    const int wm = wid & 1;          // 0..1  -> rows wm*32
    const int wn = wid >> 1;         // 0..3  -> cols wn*16
    const int q = lane >> 2, r = lane & 3;

    // staging maps
    const int arow  = tid >> 2, acol4 = (tid & 3) * 4;   // A: 64 x 16
    const int brow  = tid >> 4, bcol4 = (tid & 15) * 4;  // B-NN: 16 x 64
    const int nrow  = tid >> 2, kcol4 = (tid & 3) * 4;   // B-NT: 64 x 16

    const float* Ap = A + (size_t)(bm + arow) * lda + acol4;
    const float* Wp;
    if (!bnt) {
        int seg = bn / segw;
        Wp = W + (size_t)seg * segstride + (bn - seg * segw)
               + (size_t)brow * ldb + bcol4;
    } else {
        Wp = W + (size_t)(bn + nrow) * ldb + kcol4;
    }

    const int nk = K >> 4;

    // ---- prologue: stage tile 0 into buffer 0 ----
    float4 av = *(const float4*)Ap;
    float4 wv = *(const float4*)Wp;
    {
        float va[4] = {av.x, av.y, av.z, av.w};
        #pragma unroll
        for (int j = 0; j < 4; j++) {
            uint32_t h = f2tf32(va[j]);
            AsH[0][arow][acol4+j] = h;
            AsL[0][arow][acol4+j] = f2tf32(va[j] - __uint_as_float(h));
        }
        float vb[4] = {wv.x, wv.y, wv.z, wv.w};
        if (!bnt) {
            #pragma unroll
            for (int j = 0; j < 4; j++) {
                uint32_t h = f2tf32(vb[j]);
                BsH[0][bcol4+j][brow] = h;
                BsL[0][bcol4+j][brow] = f2tf32(vb[j] - __uint_as_float(h));
            }
        } else {
            #pragma unroll
            for (int j = 0; j < 4; j++) {
                uint32_t h = f2tf32(vb[j]);
                BsH[0][nrow][kcol4+j] = h;
                BsL[0][nrow][kcol4+j] = f2tf32(vb[j] - __uint_as_float(h));
            }
        }
    }
    __syncthreads();

    float acc[2][2][4];
    #pragma unroll
    for (int f = 0; f < 2; f++)
        #pragma unroll
        for (int g = 0; g < 2; g++)
            #pragma unroll
            for (int i = 0; i < 4; i++) acc[f][g][i] = 0.f;

    for (int t = 0; t < nk; t++) {
        int cur = t & 1, nxt = cur ^ 1;
        if (t + 1 < nk) {   // prefetch next tile into registers
            av = *(const float4*)(Ap + (size_t)(t+1)*16);
            if (!bnt) wv = *(const float4*)(Wp + (size_t)(t+1)*16*ldb);
            else      wv = *(const float4*)(Wp + (size_t)(t+1)*16);
        }
        // ---- compute on buffer cur ----
        #pragma unroll
        for (int k0 = 0; k0 < 16; k0 += 8) {
            uint32_t ah[2][4], al[2][4], bh[2][2], bl[2][2];
            #pragma unroll
            for (int f = 0; f < 2; f++) {
                int rr = wm*32 + f*16 + q;
                ah[f][0] = AsH[cur][rr  ][k0+r  ];  al[f][0] = AsL[cur][rr  ][k0+r  ];
                ah[f][1] = AsH[cur][rr+8][k0+r  ];  al[f][1] = AsL[cur][rr+8][k0+r  ];
                ah[f][2] = AsH[cur][rr  ][k0+r+4];  al[f][2] = AsL[cur][rr  ][k0+r+4];
                ah[f][3] = AsH[cur][rr+8][k0+r+4];  al[f][3] = AsL[cur][rr+8][k0+r+4];
            }
            #pragma unroll
            for (int g = 0; g < 2; g++) {
                int nn = wn*16 + g*8 + q;
                bh[g][0] = BsH[cur][nn][k0+r  ];    bl[g][0] = BsL[cur][nn][k0+r  ];
                bh[g][1] = BsH[cur][nn][k0+r+4];    bl[g][1] = BsL[cur][nn][k0+r+4];
            }
            #pragma unroll
            for (int f = 0; f < 2; f++)
                #pragma unroll
                for (int g = 0; g < 2; g++) {
                    mma_tf32(acc[f][g], ah[f], bh[g]);
                    mma_tf32(acc[f][g], ah[f], bl[g]);
                    mma_tf32(acc[f][g], al[f], bh[g]);
                }
        }
        // ---- stage next tile ----
        if (t + 1 < nk) {
            float va[4] = {av.x, av.y, av.z, av.w};
            #pragma unroll
            for (int j = 0; j < 4; j++) {
                uint32_t h = f2tf32(va[j]);
                AsH[nxt][arow][acol4+j] = h;
                AsL[nxt][arow][acol4+j] = f2tf32(va[j] - __uint_as_float(h));
            }
            float vb[4] = {wv.x, wv.y, wv.z, wv.w};
            if (!bnt) {
                #pragma unroll
                for (int j = 0; j < 4; j++) {
                    uint32_t h = f2tf32(vb[j]);
                    BsH[nxt][bcol4+j][brow] = h;
                    BsL[nxt][bcol4+j][brow] = f2tf32(vb[j] - __uint_as_float(h));
                }
            } else {
                #pragma unroll
                for (int j = 0; j < 4; j++) {
                    uint32_t h = f2tf32(vb[j]);
                    BsH[nxt][nrow][kcol4+j] = h;
                    BsL[nxt][nrow][kcol4+j] = f2tf32(vb[j] - __uint_as_float(h));
                }
            }
        }
        __syncthreads();
    }

    // ---- epilogue: C fragment layout m16n8: c0 (q, 2r), c1 (q, 2r+1),
    //                c2 (q+8, 2r), c3 (q+8, 2r+1) ----
    #pragma unroll
    for (int g = 0; g < 2; g++) {
        int ncol = bn + wn*16 + g*8 + r*2;
        float bb0 = 0.f, bb1 = 0.f;
        if (bias) { bb0 = bias[ncol]; bb1 = bias[ncol+1]; }
        #pragma unroll
        for (int f = 0; f < 2; f++) {
            #pragma unroll
            for (int h = 0; h < 2; h++) {          // h: 0 -> row q, 1 -> row q+8
                int row = bm + wm*32 + f*16 + q + h*8;
                float l0 = 0.f, l1 = 0.f;
                if (lb) {
                    const float* lp = lb + (size_t)labels[row]*N + ncol;
                    l0 = lp[0]; l1 = lp[1];
                }
                float2 v;
                v.x = acc[f][g][h*2+0] + bb0 + l0;
                v.y = acc[f][g][h*2+1] + bb1 + l1;
                if (relu) { v.x = fmaxf(v.x, 0.f); v.y = fmaxf(v.y, 0.f); }
                *(float2*)(C + (size_t)row*ldc + ncol) = v;
            }
        }
    }
}

// z-batched wrapper (head/tail nets share shapes)
__global__ __launch_bounds__(256, 2) void mma_gemm(
    const float* __restrict__ A0, const float* __restrict__ A1, int lda,
    const float* __restrict__ W0, const float* __restrict__ W1,
    int ldb, int segw, int segstride, int bnt,
    const float* __restrict__ bias0, const float* __restrict__ bias1,
    const int* __restrict__ labels,
    const float* __restrict__ lb0, const float* __restrict__ lb1,
    float* __restrict__ C0, float* __restrict__ C1, int ldc,
    int N, int K, int relu)
{
    int z = blockIdx.z;
    gemm3tf32_core(z ? A1 : A0, lda, z ? W1 : W0, ldb, segw, segstride, bnt,
                   z ? bias1 : bias0, labels, z ? lb1 : lb0,
                   z ? C1 : C0, ldc, N, K, relu);
}

// dense biaffine table: V[b][o] = U_bo @ tail_b^T   (M=N=256, K=384, NT)
__global__ __launch_bounds__(256, 2) void mma_gemm_V() {
    int bo = blockIdx.z;            // b*2+o
    int b = bo >> 1, o = bo & 1;
    const float* A  = g_u    + (size_t)b*E_*(2*H2_) + o*H2_;   // lda = 768
    const float* Bm = g_tail + (size_t)b*E_*H2_;               // ldb = 384
    float* C = g_V + (size_t)bo*E_*E_;                         // ldc = 256
    gemm3tf32_core(A, 2*H2_, Bm, H2_, E_, 0, /*bnt=*/1,
                   nullptr, nullptr, nullptr, C, E_, E_, H2_, 0);
}

// ---------------- per-entity linear terms lh/lt -----------------------------
__global__ void lhlt_kernel(const float* __restrict__ Wlin) {
    int gid  = blockIdx.x*blockDim.x + threadIdx.x;
    int w    = gid >> 5;            // entity row 0..511
    int lane = gid & 31;
    if (w >= ROWS_) return;
    float s0=0.f, s1=0.f, s2=0.f, s3=0.f;
    for (int j = lane; j < H2_; j += 32) {
        float hv = g_head[(size_t)w*H2_ + j];
        float tv = g_tail[(size_t)w*H2_ + j];
        s0 += hv * Wlin[j*2+0];
        s1 += hv * Wlin[j*2+1];
        s2 += tv * Wlin[(H2_+j)*2+0];
        s3 += tv * Wlin[(H2_+j)*2+1];
    }
    #pragma unroll
    for (int off = 16; off > 0; off >>= 1) {
        s0 += __shfl_down_sync(0xffffffffu, s0, off);
        s1 += __shfl_down_sync(0xffffffffu, s1, off);
        s2 += __shfl_down_sync(0xffffffffu, s2, off);
        s3 += __shfl_down_sync(0xffffffffu, s3, off);
    }
    if (lane == 0) {
        g_lh[w*2+0] = s0; g_lh[w*2+1] = s1;
        g_lt[w*2+0] = s2; g_lt[w*2+1] = s3;
    }
}

// ---------------- final per-pair lookup + assembly --------------------------
__global__ void gather_kernel(const int* __restrict__ hidx,
                              const int* __restrict__ tidx,
                              const float* __restrict__ blin,
                              float* __restrict__ out) {
    int gid = blockIdx.x*blockDim.x + threadIdx.x;   // B*P = 131072
    if (gid >= B_*P_) return;
    int b = gid >> 16;
    int h = hidx[gid];
    int t = tidx[gid];
    int rh = (b << 8) + h;
    int rt = (b << 8) + t;
    float v0 = g_V[((size_t)(b*2+0) << 16) + (h << 8) + t];
    float v1 = g_V[((size_t)(b*2+1) << 16) + (h << 8) + t];
    float2 r;
    r.x = v0 + g_lh[rh*2+0] + g_lt[rt*2+0] + blin[0];
    r.y = v1 + g_lh[rh*2+1] + g_lt[rt*2+1] + blin[1];
    ((float2*)out)[gid] = r;
}

// ---------------- launch ----------------------------------------------------
extern "C" void kernel_launch(void* const* d_in, const int* in_sizes, int n_in,
                              void* d_out, int out_size) {
    const float* hs   = (const float*)d_in[0];
    const float* emb  = (const float*)d_in[1];
    const float* Wh1  = (const float*)d_in[2];
    const float* bh1  = (const float*)d_in[3];
    const float* Wh2  = (const float*)d_in[4];
    const float* bh2  = (const float*)d_in[5];
    const float* Wt1  = (const float*)d_in[6];
    const float* bt1  = (const float*)d_in[7];
    const float* Wt2  = (const float*)d_in[8];
    const float* bt2  = (const float*)d_in[9];
    const float* Wbil = (const float*)d_in[10];
    const float* Wlin = (const float*)d_in[11];
    const float* blin = (const float*)d_in[12];
    const int*   est  = (const int*)d_in[13];
    const int*   een  = (const int*)d_in[14];
    const int*   elab = (const int*)d_in[15];
    const int*   hidx = (const int*)d_in[16];
    const int*   tidx = (const int*)d_in[17];

    float *p_pooled, *p_eph, *p_ept, *p_h1h, *p_h1t, *p_head, *p_tail, *p_u;
    cudaGetSymbolAddress((void**)&p_pooled, g_pooled);
    cudaGetSymbolAddress((void**)&p_eph,    g_eph);
    cudaGetSymbolAddress((void**)&p_ept,    g_ept);
    cudaGetSymbolAddress((void**)&p_h1h,    g_h1h);
    cudaGetSymbolAddress((void**)&p_h1t,    g_h1t);
    cudaGetSymbolAddress((void**)&p_head,   g_head);
    cudaGetSymbolAddress((void**)&p_tail,   g_tail);
    cudaGetSymbolAddress((void**)&p_u,      g_u);

    // 1) span mean pooling -> g_pooled [512,768]
    pool_kernel<<<ROWS_, 256>>>(hs, est, een);

    // 2) label projections for BOTH nets in one launch
    labelproj2_kernel<<<(2*NL_*H1_ + 255)/256, 256>>>(emb, Wh1, Wt1);

    // 3) FFNN layer 1 (head+tail batched, z=2):
    //    relu(pooled @ W1[:768] + b1 + e{ph,pt}[label])   K=768, N=768
    mma_gemm<<<dim3(H1_/64, ROWS_/64, 2), 256>>>(
        p_pooled, p_pooled, D_, Wh1, Wt1, H1_, H1_, 0, 0,
        bh1, bt1, elab, p_eph, p_ept, p_h1h, p_h1t, H1_, H1_, D_, 1);

    // 4) FFNN layer 2 (head+tail batched, z=2): relu(h1 @ W2 + b2)  K=768, N=384
    mma_gemm<<<dim3(H2_/64, ROWS_/64, 2), 256>>>(
        p_h1h, p_h1t, H1_, Wh2, Wt2, H2_, H2_, 0, 0,
        bh2, bt2, nullptr, nullptr, nullptr, p_head, p_tail, H2_, H2_, H1_, 1);

    // 5) per-entity linear terms (needs only head/tail)
    lhlt_kernel<<<(ROWS_*32 + 255)/256, 256>>>(Wlin);

    // 6) u = head @ W_bil (segmented-B: seg width 384, seg stride 384*384)
    mma_gemm<<<dim3((2*H2_)/64, ROWS_/64, 1), 256>>>(
        p_head, p_head, H2_, Wbil, Wbil, H2_, H2_, H2_*H2_, 0,
        nullptr, nullptr, nullptr, nullptr, nullptr, p_u, p_u, 2*H2_,
        2*H2_, H2_, 0);

    // 7) dense biaffine table V[b,o] = U_bo @ tail_b^T  (256x256x384, 4 batches)
    mma_gemm_V<<<dim3(E_/64, E_/64, B_*2), 256>>>();

    // 8) per-pair lookup + linear terms + bias
    gather_kernel<<<(B_*P_ + 255)/256, 256>>>(hidx, tidx, blin, (float*)d_out);
}

// round 6
// speedup vs baseline: 1.3117x; 1.3117x over previous
#include <cuda_runtime.h>
#include <cstdint>

// Problem constants (fixed by the reference)
#define B_    2
#define T_    512
#define D_    768
#define E_    256
#define P_    65536
#define H1_   768
#define H2_   384
#define NL_   5
#define ROWS_ (B_*E_)          // 512 fused (b,e) rows
#define VSPLIT_ 3              // split-K factor for the V GEMM (K=384 -> 128)

// ---------------- scratch (static device globals; no allocation) ------------
__device__ float g_pooled[ROWS_*D_];        // mean-pooled spans       [512,768]
__device__ float g_eph[NL_*H1_];            // emb @ Wh1[768:]         [5,768]
__device__ float g_ept[NL_*H1_];            // emb @ Wt1[768:]         [5,768]
__device__ float g_Pl1[4*ROWS_*H1_];        // L1 partials [net*2+kp][512*768]
__device__ float g_h1h[ROWS_*H1_];          // head layer-1 out        [512,768]
__device__ float g_h1t[ROWS_*H1_];          // tail layer-1 out        [512,768]
__device__ float g_Pl2[4*ROWS_*H2_];        // L2 partials [net*2+kp][512*384]
__device__ float g_head[ROWS_*H2_];         // head_all                [512,384]
__device__ float g_tail[ROWS_*H2_];         // tail_all                [512,384]
__device__ float g_Pu[2*ROWS_*2*H2_];       // u partials [kp][512*768]
__device__ float g_Vp[4*VSPLIT_*E_*E_];     // V partials [bo*3+kp][256*256]
__device__ float g_lh[ROWS_*2];             // head @ W_lin[:384]
__device__ float g_lt[ROWS_*2];             // tail @ W_lin[384:]

// ---------------- 1) span mean-pooling --------------------------------------
__global__ void pool_kernel(const float* __restrict__ hs,
                            const int* __restrict__ st,
                            const int* __restrict__ en) {
    int be = blockIdx.x;             // 0..511
    int b  = be >> 8;
    int s  = st[be];
    int len = en[be] - s;
    int cl  = len < 1 ? 1 : len;
    float inv = 1.0f / (float)cl;
    const float* base = hs + ((size_t)(b*T_ + s))*D_;
    for (int d = threadIdx.x; d < D_; d += blockDim.x) {
        float acc = 0.f;
        for (int t = 0; t < len; t++) acc += base[(size_t)t*D_ + d];
        g_pooled[(size_t)be*D_ + d] = acc * inv;
    }
}

// ---------------- 2) per-label projection through W1[768:] for BOTH nets ----
__global__ void labelproj2_kernel(const float* __restrict__ emb,
                                  const float* __restrict__ Wh1,
                                  const float* __restrict__ Wt1) {
    int gid = blockIdx.x*blockDim.x + threadIdx.x;  // 2*5*768 = 7680
    if (gid >= 2*NL_*H1_) return;
    int half = gid / (NL_*H1_);
    int r    = gid - half*(NL_*H1_);
    int l = r / H1_, n = r - l*H1_;
    const float* W1 = half ? Wt1 : Wh1;
    const float* wp = W1 + (size_t)D_*H1_ + n;      // rows 768..1535, col n
    const float* ep = emb + (size_t)l*D_;
    float acc = 0.f;
    #pragma unroll 4
    for (int k = 0; k < D_; k++) acc += ep[k] * wp[(size_t)k*H1_];
    if (half) g_ept[r] = acc; else g_eph[r] = acc;
}

// ---------------- split-K double-buffered SGEMM (partial outputs) -----------
// For blockIdx.z = z*nsplit + kp:
//   P[z*nsplit+kp] += A[z][M, kp-slice] @ W[z][kp-slice, N]   (raw, no bias)
// 64x64 block tile, BK=16, 256 threads, 4x4 register tile, 2 smem buffers,
// one __syncthreads per k-iteration. Segmented-B: element B[k][n] lives at
// W + (n/segw)*segstride + k*ldb + (n%segw).  Plain GEMMs: segw=N, segstride=0.
// M==512, N%64==0, segw%64==0, (K/nsplit)%16==0.
__global__ __launch_bounds__(256, 3) void sgemm_split(
    const float* __restrict__ A0, const float* __restrict__ A1, int lda,
    const float* __restrict__ W0, const float* __restrict__ W1,
    int ldb, int segw, int segstride,
    float* __restrict__ P, int N, int K, int nsplit)
{
    __shared__ float As[2][16][64];   // As[buf][k][m]
    __shared__ float Bs[2][16][64];   // Bs[buf][k][n]

    int zz = blockIdx.z;
    int z  = zz / nsplit;
    int kp = zz - z*nsplit;
    int kslice = K / nsplit;
    int kstart = kp * kslice;

    const float* A = z ? A1 : A0;
    const float* W = z ? W1 : W0;
    float* C = P + (size_t)zz * ROWS_ * N;

    int tid = threadIdx.x;
    int bm = blockIdx.y * 64, bn = blockIdx.x * 64;
    int tx = tid & 15, ty = tid >> 4;

    int arow = tid >> 2, ac4 = (tid & 3) * 4;     // A tile: 64 rows x 16 cols
    int brow = tid >> 4, bc4 = (tid & 15) * 4;    // W tile: 16 rows x 64 cols

    int seg = bn / segw;
    const float* Ap = A + (size_t)(bm + arow)*lda + kstart + ac4;
    const float* Wp = W + (size_t)seg*segstride + (bn - seg*segw)
                        + (size_t)(kstart + brow)*ldb + bc4;

    // prologue: load k-tile 0 into buffer 0
    float4 av = *(const float4*)Ap;
    float4 wv = *(const float4*)Wp;
    As[0][ac4+0][arow] = av.x; As[0][ac4+1][arow] = av.y;
    As[0][ac4+2][arow] = av.z; As[0][ac4+3][arow] = av.w;
    *(float4*)&Bs[0][brow][bc4] = wv;
    __syncthreads();

    float acc[4][4] = {};
    int nk = kslice >> 4;
    for (int t = 0; t < nk; t++) {
        int cur = t & 1, nxt = cur ^ 1;
        if (t + 1 < nk) {                 // prefetch next k-tile into registers
            av = *(const float4*)(Ap + (t+1)*16);
            wv = *(const float4*)(Wp + (size_t)(t+1)*16*ldb);
        }
        #pragma unroll
        for (int k = 0; k < 16; k++) {
            float4 a = *(const float4*)&As[cur][k][ty*4];
            float4 b = *(const float4*)&Bs[cur][k][tx*4];
            acc[0][0] += a.x*b.x; acc[0][1] += a.x*b.y; acc[0][2] += a.x*b.z; acc[0][3] += a.x*b.w;
            acc[1][0] += a.y*b.x; acc[1][1] += a.y*b.y; acc[1][2] += a.y*b.z; acc[1][3] += a.y*b.w;
            acc[2][0] += a.z*b.x; acc[2][1] += a.z*b.y; acc[2][2] += a.z*b.z; acc[2][3] += a.z*b.w;
            acc[3][0] += a.w*b.x; acc[3][1] += a.w*b.y; acc[3][2] += a.w*b.z; acc[3][3] += a.w*b.w;
        }
        if (t + 1 < nk) {
            As[nxt][ac4+0][arow] = av.x; As[nxt][ac4+1][arow] = av.y;
            As[nxt][ac4+2][arow] = av.z; As[nxt][ac4+3][arow] = av.w;
            *(float4*)&Bs[nxt][brow][bc4] = wv;
        }
        __syncthreads();
    }

    int ncol = bn + tx*4;
    #pragma unroll
    for (int i = 0; i < 4; i++) {
        int row = bm + ty*4 + i;
        float4 v = make_float4(acc[i][0], acc[i][1], acc[i][2], acc[i][3]);
        *(float4*)(C + (size_t)row*N + ncol) = v;
    }
}

// ---------------- combine: C[z] = relu(P[2z]+P[2z+1] + bias (+lbias)) -------
__global__ void combine2(const float* __restrict__ P,
                         const float* __restrict__ bias0,
                         const float* __restrict__ bias1,
                         const int* __restrict__ labels,
                         const float* __restrict__ lb0,
                         const float* __restrict__ lb1,
                         float* __restrict__ C0, float* __restrict__ C1, int N)
{
    int idx = blockIdx.x*blockDim.x + threadIdx.x;
    int pq = ROWS_*N/4;
    if (idx >= 2*pq) return;
    int z = idx >= pq ? 1 : 0;
    int r = idx - z*pq;
    int e = r*4;
    int row = e / N, col = e - row*N;
    const float4* P0 = (const float4*)(P + ((size_t)(z*2  ))*ROWS_*N);
    const float4* P1 = (const float4*)(P + ((size_t)(z*2+1))*ROWS_*N);
    float4 a = P0[r], b = P1[r];
    const float* bs = z ? bias1 : bias0;
    float4 v;
    v.x = a.x + b.x + bs[col];
    v.y = a.y + b.y + bs[col+1];
    v.z = a.z + b.z + bs[col+2];
    v.w = a.w + b.w + bs[col+3];
    const float* lb = z ? lb1 : lb0;
    if (lb) {
        const float* lp = lb + (size_t)labels[row]*N + col;
        v.x += lp[0]; v.y += lp[1]; v.z += lp[2]; v.w += lp[3];
    }
    v.x = fmaxf(v.x, 0.f); v.y = fmaxf(v.y, 0.f);
    v.z = fmaxf(v.z, 0.f); v.w = fmaxf(v.w, 0.f);
    (z ? (float4*)C1 : (float4*)C0)[r] = v;
}

// ---------------- dense biaffine table (NT, split-K=3, A = Pu0+Pu2 summed) --
// For blockIdx.z = bo*VSPLIT_+kp:  Vp[zz] = U_bo[:, kslice] @ tail_b[:, kslice]^T
// where U = g_Pu[0] + g_Pu[1] (u split-K partials summed during staging).
__global__ __launch_bounds__(256, 3) void sgemm_V() {
    __shared__ float As[2][16][64];
    __shared__ float Bs[2][16][64];
    int zz = blockIdx.z;                 // 0..11
    int bo = zz / VSPLIT_, kp = zz - bo*VSPLIT_;
    int b = bo >> 1, o = bo & 1;
    int kstart = kp * (H2_/VSPLIT_);     // 0,128,256
    const float* A0 = g_Pu +                     (size_t)(b*E_)*(2*H2_) + o*H2_ + kstart;
    const float* A1 = g_Pu + (size_t)ROWS_*2*H2_ + (size_t)(b*E_)*(2*H2_) + o*H2_ + kstart;
    const float* Bm = g_tail + (size_t)b*E_*H2_ + kstart;
    float* C = g_Vp + (size_t)zz*E_*E_;

    int tid = threadIdx.x;
    int bm = blockIdx.y * 64, bn = blockIdx.x * 64;
    int tx = tid & 15, ty = tid >> 4;
    int lr = tid >> 2, lc4 = (tid & 3) * 4;
    const float* Ap0 = A0 + (size_t)(bm + lr)*(2*H2_) + lc4;
    const float* Ap1 = A1 + (size_t)(bm + lr)*(2*H2_) + lc4;
    const float* Bp  = Bm + (size_t)(bn + lr)*H2_ + lc4;

    float4 a0 = *(const float4*)Ap0;
    float4 a1 = *(const float4*)Ap1;
    float4 bv = *(const float4*)Bp;
    As[0][lc4+0][lr] = a0.x + a1.x; As[0][lc4+1][lr] = a0.y + a1.y;
    As[0][lc4+2][lr] = a0.z + a1.z; As[0][lc4+3][lr] = a0.w + a1.w;
    Bs[0][lc4+0][lr] = bv.x; Bs[0][lc4+1][lr] = bv.y;
    Bs[0][lc4+2][lr] = bv.z; Bs[0][lc4+3][lr] = bv.w;
    __syncthreads();

    float acc[4][4] = {};
    const int nk = (H2_/VSPLIT_) >> 4;   // 8
    for (int t = 0; t < nk; t++) {
        int cur = t & 1, nxt = cur ^ 1;
        if (t + 1 < nk) {
            a0 = *(const float4*)(Ap0 + (t+1)*16);
            a1 = *(const float4*)(Ap1 + (t+1)*16);
            bv = *(const float4*)(Bp + (t+1)*16);
        }
        #pragma unroll
        for (int k = 0; k < 16; k++) {
            float4 a  = *(const float4*)&As[cur][k][ty*4];
            float4 bb = *(const float4*)&Bs[cur][k][tx*4];
            acc[0][0] += a.x*bb.x; acc[0][1] += a.x*bb.y; acc[0][2] += a.x*bb.z; acc[0][3] += a.x*bb.w;
            acc[1][0] += a.y*bb.x; acc[1][1] += a.y*bb.y; acc[1][2] += a.y*bb.z; acc[1][3] += a.y*bb.w;
            acc[2][0] += a.z*bb.x; acc[2][1] += a.z*bb.y; acc[2][2] += a.z*bb.z; acc[2][3] += a.z*bb.w;
            acc[3][0] += a.w*bb.x; acc[3][1] += a.w*bb.y; acc[3][2] += a.w*bb.z; acc[3][3] += a.w*bb.w;
        }
        if (t + 1 < nk) {
            As[nxt][lc4+0][lr] = a0.x + a1.x; As[nxt][lc4+1][lr] = a0.y + a1.y;
            As[nxt][lc4+2][lr] = a0.z + a1.z; As[nxt][lc4+3][lr] = a0.w + a1.w;
            Bs[nxt][lc4+0][lr] = bv.x; Bs[nxt][lc4+1][lr] = bv.y;
            Bs[nxt][lc4+2][lr] = bv.z; Bs[nxt][lc4+3][lr] = bv.w;
        }
        __syncthreads();
    }
    #pragma unroll
    for (int i = 0; i < 4; i++) {
        float4 v = make_float4(acc[i][0], acc[i][1], acc[i][2], acc[i][3]);
        *(float4*)(C + (size_t)(bm + ty*4 + i)*E_ + bn + tx*4) = v;
    }
}

// ---------------- per-entity linear terms lh/lt -----------------------------
__global__ void lhlt_kernel(const float* __restrict__ Wlin) {
    int gid  = blockIdx.x*blockDim.x + threadIdx.x;
    int w    = gid >> 5;            // entity row 0..511
    int lane = gid & 31;
    if (w >= ROWS_) return;
    float s0=0.f, s1=0.f, s2=0.f, s3=0.f;
    for (int j = lane; j < H2_; j += 32) {
        float hv = g_head[(size_t)w*H2_ + j];
        float tv = g_tail[(size_t)w*H2_ + j];
        s0 += hv * Wlin[j*2+0];
        s1 += hv * Wlin[j*2+1];
        s2 += tv * Wlin[(H2_+j)*2+0];
        s3 += tv * Wlin[(H2_+j)*2+1];
    }
    #pragma unroll
    for (int off = 16; off > 0; off >>= 1) {
        s0 += __shfl_down_sync(0xffffffffu, s0, off);
        s1 += __shfl_down_sync(0xffffffffu, s1, off);
        s2 += __shfl_down_sync(0xffffffffu, s2, off);
        s3 += __shfl_down_sync(0xffffffffu, s3, off);
    }
    if (lane == 0) {
        g_lh[w*2+0] = s0; g_lh[w*2+1] = s1;
        g_lt[w*2+0] = s2; g_lt[w*2+1] = s3;
    }
}

// ---------------- final per-pair lookup (sums V partials) -------------------
__global__ void gather_kernel(const int* __restrict__ hidx,
                              const int* __restrict__ tidx,
                              const float* __restrict__ blin,
                              float* __restrict__ out) {
    int gid = blockIdx.x*blockDim.x + threadIdx.x;   // B*P = 131072
    if (gid >= B_*P_) return;
    int b = gid >> 16;
    int h = hidx[gid];
    int t = tidx[gid];
    int rh = (b << 8) + h;
    int rt = (b << 8) + t;
    size_t off = (size_t)(h << 8) + t;
    float v0 = 0.f, v1 = 0.f;
    #pragma unroll
    for (int kp = 0; kp < VSPLIT_; kp++) {
        v0 += g_Vp[(((size_t)(b*2+0)*VSPLIT_ + kp) << 16) + off];
        v1 += g_Vp[(((size_t)(b*2+1)*VSPLIT_ + kp) << 16) + off];
    }
    float2 r;
    r.x = v0 + g_lh[rh*2+0] + g_lt[rt*2+0] + blin[0];
    r.y = v1 + g_lh[rh*2+1] + g_lt[rt*2+1] + blin[1];
    ((float2*)out)[gid] = r;
}

// ---------------- launch ----------------------------------------------------
extern "C" void kernel_launch(void* const* d_in, const int* in_sizes, int n_in,
                              void* d_out, int out_size) {
    const float* hs   = (const float*)d_in[0];
    const float* emb  = (const float*)d_in[1];
    const float* Wh1  = (const float*)d_in[2];
    const float* bh1  = (const float*)d_in[3];
    const float* Wh2  = (const float*)d_in[4];
    const float* bh2  = (const float*)d_in[5];
    const float* Wt1  = (const float*)d_in[6];
    const float* bt1  = (const float*)d_in[7];
    const float* Wt2  = (const float*)d_in[8];
    const float* bt2  = (const float*)d_in[9];
    const float* Wbil = (const float*)d_in[10];
    const float* Wlin = (const float*)d_in[11];
    const float* blin = (const float*)d_in[12];
    const int*   est  = (const int*)d_in[13];
    const int*   een  = (const int*)d_in[14];
    const int*   elab = (const int*)d_in[15];
    const int*   hidx = (const int*)d_in[16];
    const int*   tidx = (const int*)d_in[17];

    float *p_pooled, *p_eph, *p_ept, *p_Pl1, *p_h1h, *p_h1t,
          *p_Pl2, *p_head, *p_tail, *p_Pu;
    cudaGetSymbolAddress((void**)&p_pooled, g_pooled);
    cudaGetSymbolAddress((void**)&p_eph,    g_eph);
    cudaGetSymbolAddress((void**)&p_ept,    g_ept);
    cudaGetSymbolAddress((void**)&p_Pl1,    g_Pl1);
    cudaGetSymbolAddress((void**)&p_h1h,    g_h1h);
    cudaGetSymbolAddress((void**)&p_h1t,    g_h1t);
    cudaGetSymbolAddress((void**)&p_Pl2,    g_Pl2);
    cudaGetSymbolAddress((void**)&p_head,   g_head);
    cudaGetSymbolAddress((void**)&p_tail,   g_tail);
    cudaGetSymbolAddress((void**)&p_Pu,     g_Pu);

    // 1) span mean pooling -> g_pooled [512,768]
    pool_kernel<<<ROWS_, 256>>>(hs, est, een);

    // 2) label projections for BOTH nets in one launch
    labelproj2_kernel<<<(2*NL_*H1_ + 255)/256, 256>>>(emb, Wh1, Wt1);

    // 3) FFNN layer 1 partials (head+tail nets x split-K2): 384 blocks
    sgemm_split<<<dim3(H1_/64, ROWS_/64, 4), 256>>>(
        p_pooled, p_pooled, D_, Wh1, Wt1, H1_, H1_, 0,
        p_Pl1, H1_, D_, 2);

    // 3b) combine + bias + label-bias + relu -> h1h/h1t
    combine2<<<(2*ROWS_*H1_/4 + 255)/256, 256>>>(
        p_Pl1, bh1, bt1, elab, p_eph, p_ept, p_h1h, p_h1t, H1_);

    // 4) FFNN layer 2 partials (head+tail x split-K2): 192 blocks
    sgemm_split<<<dim3(H2_/64, ROWS_/64, 4), 256>>>(
        p_h1h, p_h1t, H1_, Wh2, Wt2, H2_, H2_, 0,
        p_Pl2, H2_, H1_, 2);

    // 4b) combine + bias + relu -> head/tail
    combine2<<<(2*ROWS_*H2_/4 + 255)/256, 256>>>(
        p_Pl2, bh2, bt2, nullptr, nullptr, nullptr, p_head, p_tail, H2_);

    // 5) per-entity linear terms (needs only head/tail)
    lhlt_kernel<<<(ROWS_*32 + 255)/256, 256>>>(Wlin);

    // 6) u partials = head @ W_bil (segmented-B), split-K2: 192 blocks
    sgemm_split<<<dim3((2*H2_)/64, ROWS_/64, 2), 256>>>(
        p_head, p_head, H2_, Wbil, Wbil, H2_, H2_, H2_*H2_,
        p_Pu, 2*H2_, H2_, 2);

    // 7) V partials = (Pu0+Pu1) @ tail^T, split-K3: 192 blocks
    sgemm_V<<<dim3(E_/64, E_/64, B_*2*VSPLIT_), 256>>>();

    // 8) per-pair lookup (sums V partials) + linear terms + bias
    gather_kernel<<<(B_*P_ + 255)/256, 256>>>(hidx, tidx, blin, (float*)d_out);
}

// round 8
// speedup vs baseline: 1.3122x; 1.0004x over previous
#include <cuda_runtime.h>
#include <cstdint>

// Problem constants (fixed by the reference)
#define B_    2
#define T_    512
#define D_    768
#define E_    256
#define P_    65536
#define H1_   768
#define H2_   384
#define NL_   5
#define ROWS_ (B_*E_)          // 512 fused (b,e) rows

#define PL1_SLAB (ROWS_*H1_)   // 393216
#define PL2_SLAB (ROWS_*H2_)   // 196608
#define PU_SLAB  (ROWS_*2*H2_) // 393216

// ---------------- scratch (static device globals; no allocation) ------------
__device__ float g_pooled[ROWS_*D_];        // mean-pooled spans       [512,768]
__device__ float g_eph[NL_*H1_];            // emb @ Wh1[768:]         [5,768]
__device__ float g_ept[NL_*H1_];            // emb @ Wt1[768:]         [5,768]
__device__ float g_Pl1[4*PL1_SLAB];         // L1 partials [net*2+kp]
__device__ float g_Pl2[8*PL2_SLAB];         // L2 partials [net*4+kp]
__device__ float g_head[ROWS_*H2_];         // head_all                [512,384]
__device__ float g_tail[ROWS_*H2_];         // tail_all                [512,384]
__device__ float g_Pu[4*PU_SLAB];           // u partials [kp]
__device__ float g_Vp[16*E_*E_];            // V partials [bo*4+kp][256*256]
__device__ float g_lh[ROWS_*2];             // head @ W_lin[:384]
__device__ float g_lt[ROWS_*2];             // tail @ W_lin[384:]

// ---------------- tf32 helpers ----------------------------------------------
__device__ __forceinline__ uint32_t f2tf32(float x) {
    uint32_t r;
    asm("cvt.rna.tf32.f32 %0, %1;" : "=r"(r) : "f"(x));
    return r;
}
__device__ __forceinline__ void mma_tf32(float c[4],
                                         const uint32_t a[4],
                                         const uint32_t b[2]) {
    asm volatile(
        "mma.sync.aligned.m16n8k8.row.col.f32.tf32.tf32.f32 "
        "{%0,%1,%2,%3}, {%4,%5,%6,%7}, {%8,%9}, {%0,%1,%2,%3};"
        : "+f"(c[0]), "+f"(c[1]), "+f"(c[2]), "+f"(c[3])
        : "r"(a[0]), "r"(a[1]), "r"(a[2]), "r"(a[3]), "r"(b[0]), "r"(b[1]));
}
__device__ __forceinline__ uint32_t ldb32(const float* p) {
    return __float_as_uint(*p);
}

// smem layout (floats):  As stride 20 per row, Bs stride 72 per k-row
#define ASTRIDE 20
#define BSTRIDE 72
#define AS_BUF  (128*ASTRIDE)   // 2560
#define BS_BUF  (16*BSTRIDE)    // 1152
#define SM_AH   0
#define SM_AL   (2*AS_BUF)      // 5120
#define SM_BH   (4*AS_BUF)      // 10240
#define SM_BL   (4*AS_BUF + 2*BS_BUF)  // 12544
#define SM_FLOATS (4*AS_BUF + 4*BS_BUF) // 14848
#define SM_BYTES  (SM_FLOATS*4)         // 59392

// ---------------- 3xTF32 GEMM core ------------------------------------------
// Block tile 128(M) x 64(N), BK=16, 256 threads = 8 warps (4 m-warps x 2
// n-warps), warp tile 32x32 (2 m-frags x 4 n-frags of m16n8k8).
// Each input split x = hi + lo in tf32 during smem staging; accumulate
// hi*hi + hi*lo + lo*hi in fp32.
// AMODE: 0 = plain A0.
//        1 = relu(A0 + A1 + abias[k] + albias[labels[row]][k])  (fused L1 combine)
//        2 = A0 + A1 + A2 + A3 (sum of 4 split-K partials)
// BMODE: 0 = NN, B[k][n] at W + (n/segw)*segstride + k*ldb + (n%segw)
//        1 = NT, B[n][k] at W + n*ldb + k
// M%128==0, N%64==0, segw%64==0, kslice%16==0.
template<int AMODE, int BMODE>
__device__ __forceinline__ void gemm_core(
    const float* __restrict__ A0, const float* __restrict__ A1,
    const float* __restrict__ A2, const float* __restrict__ A3,
    const float* __restrict__ abias, const int* __restrict__ labels,
    const float* __restrict__ albias, int lda,
    const float* __restrict__ W, int ldb, int segw, int segstride,
    float* __restrict__ C, int N, int kstart, int kslice)
{
    extern __shared__ float sm[];
    float* AsH = sm + SM_AH;
    float* AsL = sm + SM_AL;
    float* BsH = sm + SM_BH;
    float* BsL = sm + SM_BL;

    const int tid = threadIdx.x;
    const int bm = blockIdx.y * 128, bn = blockIdx.x * 64;
    const int lane = tid & 31, wid = tid >> 5;
    const int wm = wid & 3, wn = wid >> 2;     // 4 x 2 warp grid
    const int q = lane >> 2, r = lane & 3;

    // staging maps
    const int arow = tid >> 1, ac8 = (tid & 1) * 8;   // A: 128 rows x 16 k
    const int brow = tid >> 4, bc4 = (tid & 15) * 4;  // B NN: 16 k x 64 n
    const int nrow = tid >> 2, kc4 = (tid & 3) * 4;   // B NT: 64 n x 16 k

    const float* Ap0 = A0 + (size_t)(bm+arow)*lda + kstart + ac8;
    const float* Ap1 = (AMODE>=1) ? A1 + (size_t)(bm+arow)*lda + kstart + ac8 : nullptr;
    const float* Ap2 = (AMODE==2) ? A2 + (size_t)(bm+arow)*lda + kstart + ac8 : nullptr;
    const float* Ap3 = (AMODE==2) ? A3 + (size_t)(bm+arow)*lda + kstart + ac8 : nullptr;
    const float* biasp = (AMODE==1) ? abias + kstart + ac8 : nullptr;
    const float* lbp   = (AMODE==1)
        ? albias + (size_t)labels[bm+arow]*lda + kstart + ac8 : nullptr;

    const float* Wp;
    if (BMODE == 0) {
        int seg = bn / segw;
        Wp = W + (size_t)seg*segstride + (bn - seg*segw)
               + (size_t)(kstart+brow)*ldb + bc4;
    } else {
        Wp = W + (size_t)(bn + nrow)*ldb + kstart + kc4;
    }

    float va[8], vb[4];

    auto fetchA = [&](int t) {
        const float* p = Ap0 + t*16;
        float4 x0 = *(const float4*)p, x1 = *(const float4*)(p+4);
        va[0]=x0.x; va[1]=x0.y; va[2]=x0.z; va[3]=x0.w;
        va[4]=x1.x; va[5]=x1.y; va[6]=x1.z; va[7]=x1.w;
        if (AMODE == 1) {
            const float* p1 = Ap1 + t*16;
            float4 y0 = *(const float4*)p1, y1 = *(const float4*)(p1+4);
            float4 b0 = *(const float4*)(biasp + t*16), b1 = *(const float4*)(biasp + t*16 + 4);
            float4 l0 = *(const float4*)(lbp + t*16),   l1 = *(const float4*)(lbp + t*16 + 4);
            float ys[8] = {y0.x,y0.y,y0.z,y0.w,y1.x,y1.y,y1.z,y1.w};
            float bs[8] = {b0.x,b0.y,b0.z,b0.w,b1.x,b1.y,b1.z,b1.w};
            float ls[8] = {l0.x,l0.y,l0.z,l0.w,l1.x,l1.y,l1.z,l1.w};
            #pragma unroll
            for (int j = 0; j < 8; j++) {
                float v = va[j] + ys[j] + bs[j];
                v += ls[j];
                va[j] = fmaxf(v, 0.f);
            }
        } else if (AMODE == 2) {
            const float* p1 = Ap1 + t*16;
            const float* p2 = Ap2 + t*16;
            const float* p3 = Ap3 + t*16;
            float4 y0 = *(const float4*)p1, y1 = *(const float4*)(p1+4);
            float4 z0 = *(const float4*)p2, z1 = *(const float4*)(p2+4);
            float4 w0 = *(const float4*)p3, w1 = *(const float4*)(p3+4);
            float ys[8] = {y0.x,y0.y,y0.z,y0.w,y1.x,y1.y,y1.z,y1.w};
            float zs[8] = {z0.x,z0.y,z0.z,z0.w,z1.x,z1.y,z1.z,z1.w};
            float ws[8] = {w0.x,w0.y,w0.z,w0.w,w1.x,w1.y,w1.z,w1.w};
            #pragma unroll
            for (int j = 0; j < 8; j++)
                va[j] = ((va[j] + ys[j]) + zs[j]) + ws[j];
        }
    };
    auto fetchB = [&](int t) {
        float4 w4;
        if (BMODE == 0) w4 = *(const float4*)(Wp + (size_t)t*16*ldb);
        else            w4 = *(const float4*)(Wp + t*16);
        vb[0]=w4.x; vb[1]=w4.y; vb[2]=w4.z; vb[3]=w4.w;
    };
    auto stageA = [&](int buf) {
        int base = buf*AS_BUF + arow*ASTRIDE + ac8;
        #pragma unroll
        for (int j = 0; j < 8; j++) {
            uint32_t h = f2tf32(va[j]);
            AsH[base+j] = __uint_as_float(h);
            AsL[base+j] = __uint_as_float(f2tf32(va[j] - __uint_as_float(h)));
        }
    };
    auto stageB = [&](int buf) {
        if (BMODE == 0) {
            int base = buf*BS_BUF + brow*BSTRIDE + bc4;
            #pragma unroll
            for (int j = 0; j < 4; j++) {
                uint32_t h = f2tf32(vb[j]);
                BsH[base+j] = __uint_as_float(h);
                BsL[base+j] = __uint_as_float(f2tf32(vb[j] - __uint_as_float(h)));
            }
        } else {
            int base = buf*BS_BUF + nrow;
            #pragma unroll
            for (int j = 0; j < 4; j++) {
                uint32_t h = f2tf32(vb[j]);
                BsH[base + (kc4+j)*BSTRIDE] = __uint_as_float(h);
                BsL[base + (kc4+j)*BSTRIDE] = __uint_as_float(f2tf32(vb[j] - __uint_as_float(h)));
            }
        }
    };

    float acc[2][4][4];
    #pragma unroll
    for (int f = 0; f < 2; f++)
        #pragma unroll
        for (int g = 0; g < 4; g++)
            #pragma unroll
            for (int i = 0; i < 4; i++) acc[f][g][i] = 0.f;

    fetchA(0); fetchB(0);
    stageA(0); stageB(0);
    __syncthreads();

    const int nk = kslice >> 4;
    for (int t = 0; t < nk; t++) {
        int cur = t & 1, nxt = cur ^ 1;
        if (t + 1 < nk) { fetchA(t+1); fetchB(t+1); }

        #pragma unroll
        for (int k0 = 0; k0 < 16; k0 += 8) {
            uint32_t ah[2][4], al[2][4], bh[4][2], bl[4][2];
            #pragma unroll
            for (int f = 0; f < 2; f++) {
                int m = wm*32 + f*16 + q;
                int ab = cur*AS_BUF + m*ASTRIDE + k0 + r;
                ah[f][0] = ldb32(AsH + ab);
                ah[f][1] = ldb32(AsH + ab + 8*ASTRIDE);
                ah[f][2] = ldb32(AsH + ab + 4);
                ah[f][3] = ldb32(AsH + ab + 8*ASTRIDE + 4);
                al[f][0] = ldb32(AsL + ab);
                al[f][1] = ldb32(AsL + ab + 8*ASTRIDE);
                al[f][2] = ldb32(AsL + ab + 4);
                al[f][3] = ldb32(AsL + ab + 8*ASTRIDE + 4);
            }
            #pragma unroll
            for (int g = 0; g < 4; g++) {
                int nn = wn*32 + g*8 + q;
                int bb = cur*BS_BUF + (k0+r)*BSTRIDE + nn;
                bh[g][0] = ldb32(BsH + bb);
                bh[g][1] = ldb32(BsH + bb + 4*BSTRIDE);
                bl[g][0] = ldb32(BsL + bb);
                bl[g][1] = ldb32(BsL + bb + 4*BSTRIDE);
            }
            #pragma unroll
            for (int f = 0; f < 2; f++)
                #pragma unroll
                for (int g = 0; g < 4; g++) {
                    mma_tf32(acc[f][g], ah[f], bh[g]);
                    mma_tf32(acc[f][g], ah[f], bl[g]);
                    mma_tf32(acc[f][g], al[f], bh[g]);
                }
        }

        if (t + 1 < nk) { stageA(nxt); stageB(nxt); }
        __syncthreads();
    }

    // epilogue: m16n8 frag: c0 (q, 2r), c1 (q, 2r+1), c2 (q+8, 2r), c3 (q+8, 2r+1)
    #pragma unroll
    for (int f = 0; f < 2; f++) {
        int row0 = bm + wm*32 + f*16 + q;
        #pragma unroll
        for (int g = 0; g < 4; g++) {
            int ncol = bn + wn*32 + g*8 + r*2;
            *(float2*)(C + (size_t)row0*N + ncol) =
                make_float2(acc[f][g][0], acc[f][g][1]);
            *(float2*)(C + (size_t)(row0+8)*N + ncol) =
                make_float2(acc[f][g][2], acc[f][g][3]);
        }
    }
}

// ---------------- GEMM wrappers ---------------------------------------------
// L1: Pl1[net*2+kp] = pooled @ W1[net]   grid(12,4,4)
__global__ __launch_bounds__(256, 2) void k_l1(
    const float* __restrict__ pooled,
    const float* __restrict__ Wh1, const float* __restrict__ Wt1,
    float* __restrict__ Pl1)
{
    int z = blockIdx.z, net = z >> 1, kp = z & 1;
    gemm_core<0,0>(pooled, nullptr, nullptr, nullptr,
                   nullptr, nullptr, nullptr, D_,
                   net ? Wt1 : Wh1, H1_, H1_, 0,
                   Pl1 + (size_t)z*PL1_SLAB, H1_, kp*384, 384);
}

// L2: Pl2[net*4+kp] = relu(Pl1sum+b1+lb) @ W2[net]   grid(6,4,8)
__global__ __launch_bounds__(256, 2) void k_l2(
    const float* __restrict__ Pl1,
    const float* __restrict__ Wh2, const float* __restrict__ Wt2,
    const float* __restrict__ bh1, const float* __restrict__ bt1,
    const int* __restrict__ labels,
    const float* __restrict__ eph, const float* __restrict__ ept,
    float* __restrict__ Pl2)
{
    int z = blockIdx.z, net = z >> 2, kp = z & 3;
    gemm_core<1,0>(Pl1 + (size_t)(net*2)*PL1_SLAB,
                   Pl1 + (size_t)(net*2+1)*PL1_SLAB, nullptr, nullptr,
                   net ? bt1 : bh1, labels, net ? ept : eph, H1_,
                   net ? Wt2 : Wh2, H2_, H2_, 0,
                   Pl2 + (size_t)z*PL2_SLAB, H2_, kp*192, 192);
}

// u: Pu[kp] = head @ W_bil (segmented)   grid(12,4,4)
__global__ __launch_bounds__(256, 2) void k_u(
    const float* __restrict__ head, const float* __restrict__ Wbil,
    float* __restrict__ Pu)
{
    int kp = blockIdx.z;
    gemm_core<0,0>(head, nullptr, nullptr, nullptr,
                   nullptr, nullptr, nullptr, H2_,
                   Wbil, H2_, H2_, H2_*H2_,
                   Pu + (size_t)kp*PU_SLAB, 2*H2_, kp*96, 96);
}

// V: Vp[bo*4+kp] = (sum4 Pu)[b, :, o-slice] @ tail_b^T   grid(4,2,16)
__global__ __launch_bounds__(256, 2) void k_V(
    const float* __restrict__ Pu, const float* __restrict__ tail,
    float* __restrict__ Vp)
{
    int z = blockIdx.z, bo = z >> 2, kp = z & 3;
    int b = bo >> 1, o = bo & 1;
    const float* base = Pu + (size_t)(b*E_)*(2*H2_) + o*H2_;
    gemm_core<2,1>(base, base + PU_SLAB, base + 2*PU_SLAB, base + 3*PU_SLAB,
                   nullptr, nullptr, nullptr, 2*H2_,
                   tail + (size_t)b*E_*H2_, H2_, 0, 0,
                   Vp + (size_t)z*E_*E_, E_, kp*96, 96);
}

// ---------------- 1) span mean-pooling --------------------------------------
__global__ void pool_kernel(const float* __restrict__ hs,
                            const int* __restrict__ st,
                            const int* __restrict__ en) {
    int be = blockIdx.x;             // 0..511
    int b  = be >> 8;
    int s  = st[be];
    int len = en[be] - s;
    int cl  = len < 1 ? 1 : len;
    float inv = 1.0f / (float)cl;
    const float* base = hs + ((size_t)(b*T_ + s))*D_;
    for (int d = threadIdx.x; d < D_; d += blockDim.x) {
        float acc = 0.f;
        for (int t = 0; t < len; t++) acc += base[(size_t)t*D_ + d];
        g_pooled[(size_t)be*D_ + d] = acc * inv;
    }
}

// ---------------- 2) per-label projection through W1[768:] for BOTH nets ----
__global__ void labelproj2_kernel(const float* __restrict__ emb,
                                  const float* __restrict__ Wh1,
                                  const float* __restrict__ Wt1) {
    int gid = blockIdx.x*blockDim.x + threadIdx.x;  // 2*5*768 = 7680
    if (gid >= 2*NL_*H1_) return;
    int half = gid / (NL_*H1_);
    int r    = gid - half*(NL_*H1_);
    int l = r / H1_, n = r - l*H1_;
    const float* W1 = half ? Wt1 : Wh1;
    const float* wp = W1 + (size_t)D_*H1_ + n;      // rows 768..1535, col n
    const float* ep = emb + (size_t)l*D_;
    float acc = 0.f;
    #pragma unroll 4
    for (int k = 0; k < D_; k++) acc += ep[k] * wp[(size_t)k*H1_];
    if (half) g_ept[r] = acc; else g_eph[r] = acc;
}

// ---------------- combine L2: head/tail = relu(sum4 Pl2 + bias) -------------
__global__ void combine_l2(const float* __restrict__ Pl2,
                           const float* __restrict__ bh2,
                           const float* __restrict__ bt2,
                           float* __restrict__ head, float* __restrict__ tail)
{
    int idx = blockIdx.x*blockDim.x + threadIdx.x;
    int pq = ROWS_*H2_/4;
    if (idx >= 2*pq) return;
    int net = idx >= pq ? 1 : 0;
    int r = idx - net*pq;
    int col = (r*4) % H2_;
    const float4* P0 = (const float4*)(Pl2 + (size_t)(net*4+0)*PL2_SLAB);
    const float4* P1 = (const float4*)(Pl2 + (size_t)(net*4+1)*PL2_SLAB);
    const float4* P2 = (const float4*)(Pl2 + (size_t)(net*4+2)*PL2_SLAB);
    const float4* P3 = (const float4*)(Pl2 + (size_t)(net*4+3)*PL2_SLAB);
    float4 a = P0[r], b = P1[r], c = P2[r], d = P3[r];
    const float* bs = net ? bt2 : bh2;
    float4 v;
    v.x = ((a.x + b.x) + c.x) + d.x + bs[col];
    v.y = ((a.y + b.y) + c.y) + d.y + bs[col+1];
    v.z = ((a.z + b.z) + c.z) + d.z + bs[col+2];
    v.w = ((a.w + b.w) + c.w) + d.w + bs[col+3];
    v.x = fmaxf(v.x, 0.f); v.y = fmaxf(v.y, 0.f);
    v.z = fmaxf(v.z, 0.f); v.w = fmaxf(v.w, 0.f);
    (net ? (float4*)tail : (float4*)head)[r] = v;
}

// ---------------- per-entity linear terms lh/lt -----------------------------
__global__ void lhlt_kernel(const float* __restrict__ Wlin) {
    int gid  = blockIdx.x*blockDim.x + threadIdx.x;
    int w    = gid >> 5;            // entity row 0..511
    int lane = gid & 31;
    if (w >= ROWS_) return;
    float s0=0.f, s1=0.f, s2=0.f, s3=0.f;
    for (int j = lane; j < H2_; j += 32) {
        float hv = g_head[(size_t)w*H2_ + j];
        float tv = g_tail[(size_t)w*H2_ + j];
        s0 += hv * Wlin[j*2+0];
        s1 += hv * Wlin[j*2+1];
        s2 += tv * Wlin[(H2_+j)*2+0];
        s3 += tv * Wlin[(H2_+j)*2+1];
    }
    #pragma unroll
    for (int off = 16; off > 0; off >>= 1) {
        s0 += __shfl_down_sync(0xffffffffu, s0, off);
        s1 += __shfl_down_sync(0xffffffffu, s1, off);
        s2 += __shfl_down_sync(0xffffffffu, s2, off);
        s3 += __shfl_down_sync(0xffffffffu, s3, off);
    }
    if (lane == 0) {
        g_lh[w*2+0] = s0; g_lh[w*2+1] = s1;
        g_lt[w*2+0] = s2; g_lt[w*2+1] = s3;
    }
}

// ---------------- final per-pair lookup (sums 4 V partials per o) -----------
__global__ void gather_kernel(const int* __restrict__ hidx,
                              const int* __restrict__ tidx,
                              const float* __restrict__ blin,
                              float* __restrict__ out) {
    int gid = blockIdx.x*blockDim.x + threadIdx.x;   // B*P = 131072
    if (gid >= B_*P_) return;
    int b = gid >> 16;
    int h = hidx[gid];
    int t = tidx[gid];
    int rh = (b << 8) + h;
    int rt = (b << 8) + t;
    size_t off = (size_t)(h << 8) + t;
    float v0 = 0.f, v1 = 0.f;
    #pragma unroll
    for (int kp = 0; kp < 4; kp++) {
        v0 += g_Vp[(((size_t)(b*2+0)*4 + kp) << 16) + off];
        v1 += g_Vp[(((size_t)(b*2+1)*4 + kp) << 16) + off];
    }
    float2 r;
    r.x = v0 + g_lh[rh*2+0] + g_lt[rt*2+0] + blin[0];
    r.y = v1 + g_lh[rh*2+1] + g_lt[rt*2+1] + blin[1];
    ((float2*)out)[gid] = r;
}

// ---------------- launch ----------------------------------------------------
extern "C" void kernel_launch(void* const* d_in, const int* in_sizes, int n_in,
                              void* d_out, int out_size) {
    const float* hs   = (const float*)d_in[0];
    const float* emb  = (const float*)d_in[1];
    const float* Wh1  = (const float*)d_in[2];
    const float* bh1  = (const float*)d_in[3];
    const float* Wh2  = (const float*)d_in[4];
    const float* bh2  = (const float*)d_in[5];
    const float* Wt1  = (const float*)d_in[6];
    const float* bt1  = (const float*)d_in[7];
    const float* Wt2  = (const float*)d_in[8];
    const float* bt2  = (const float*)d_in[9];
    const float* Wbil = (const float*)d_in[10];
    const float* Wlin = (const float*)d_in[11];
    const float* blin = (const float*)d_in[12];
    const int*   est  = (const int*)d_in[13];
    const int*   een  = (const int*)d_in[14];
    const int*   elab = (const int*)d_in[15];
    const int*   hidx = (const int*)d_in[16];
    const int*   tidx = (const int*)d_in[17];

    float *p_pooled, *p_eph, *p_ept, *p_Pl1, *p_Pl2, *p_head, *p_tail,
          *p_Pu, *p_Vp;
    cudaGetSymbolAddress((void**)&p_pooled, g_pooled);
    cudaGetSymbolAddress((void**)&p_eph,    g_eph);
    cudaGetSymbolAddress((void**)&p_ept,    g_ept);
    cudaGetSymbolAddress((void**)&p_Pl1,    g_Pl1);
    cudaGetSymbolAddress((void**)&p_Pl2,    g_Pl2);
    cudaGetSymbolAddress((void**)&p_head,   g_head);
    cudaGetSymbolAddress((void**)&p_tail,   g_tail);
    cudaGetSymbolAddress((void**)&p_Pu,     g_Pu);
    cudaGetSymbolAddress((void**)&p_Vp,     g_Vp);

    // allow >48KB dynamic smem on the GEMM kernels (non-stream API; capture-safe)
    cudaFuncSetAttribute(k_l1, cudaFuncAttributeMaxDynamicSharedMemorySize, SM_BYTES);
    cudaFuncSetAttribute(k_l2, cudaFuncAttributeMaxDynamicSharedMemorySize, SM_BYTES);
    cudaFuncSetAttribute(k_u,  cudaFuncAttributeMaxDynamicSharedMemorySize, SM_BYTES);
    cudaFuncSetAttribute(k_V,  cudaFuncAttributeMaxDynamicSharedMemorySize, SM_BYTES);

    // 1) span mean pooling -> g_pooled [512,768]
    pool_kernel<<<ROWS_, 256>>>(hs, est, een);

    // 2) label projections for BOTH nets in one launch
    labelproj2_kernel<<<(2*NL_*H1_ + 255)/256, 256>>>(emb, Wh1, Wt1);

    // 3) L1 partials (2 nets x split-K2): 192 blocks
    k_l1<<<dim3(H1_/64, ROWS_/128, 4), 256, SM_BYTES>>>(p_pooled, Wh1, Wt1, p_Pl1);

    // 4) L2 partials with fused L1-combine in A-staging (2 nets x split-K4): 192 blocks
    k_l2<<<dim3(H2_/64, ROWS_/128, 8), 256, SM_BYTES>>>(
        p_Pl1, Wh2, Wt2, bh1, bt1, elab, p_eph, p_ept, p_Pl2);

    // 5) combine L2 partials -> head/tail
    combine_l2<<<(2*ROWS_*H2_/4 + 255)/256, 256>>>(p_Pl2, bh2, bt2, p_head, p_tail);

    // 6) per-entity linear terms
    lhlt_kernel<<<(ROWS_*32 + 255)/256, 256>>>(Wlin);

    // 7) u partials = head @ W_bil (segmented-B), split-K4: 192 blocks
    k_u<<<dim3((2*H2_)/64, ROWS_/128, 4), 256, SM_BYTES>>>(p_head, Wbil, p_Pu);

    // 8) V partials = (sum4 Pu) @ tail^T, per (b,o) x split-K4: 128 blocks
    k_V<<<dim3(E_/64, E_/128, 16), 256, SM_BYTES>>>(p_Pu, p_tail, p_Vp);

    // 9) per-pair lookup (sums V partials) + linear terms + bias
    gather_kernel<<<(B_*P_ + 255)/256, 256>>>(hidx, tidx, blin, (float*)d_out);
}